// round 1
// baseline (speedup 1.0000x reference)
#include <cuda_runtime.h>
#include <math.h>

#define BATCH 8192
#define NCLS  10
#define FEAT  64
#define HID   128
#define KTOT  (NCLS * HID)   // 1280

// Scratch (static device arrays: allocation-free per harness rules)
__device__ float g_Y[(size_t)BATCH * KTOT];   // relu(x @ G1 + g1), [8192][1280]  (~42 MB)
__device__ float g_E[NCLS * HID * HID];       // E_i = G2 @ D1_i, [10][128][128]
__device__ float g_c0[HID];                   // d1 + sum_i g2 @ D1_i

// ---------------------------------------------------------------------------
// Kernel 0: precompute E and c0 (cheap, rerun every launch for determinism)
// grid = 41 blocks: bx in [0,40) -> E tiles, bx == 40 -> c0
// ---------------------------------------------------------------------------
__global__ void __launch_bounds__(256) prep_kernel(
    const float* __restrict__ G2, const float* __restrict__ g2,
    const float* __restrict__ D1, const float* __restrict__ d1)
{
    const int bx = blockIdx.x;
    const int t  = threadIdx.x;

    if (bx == 40) {
        __shared__ float sg2[128];
        if (t < 128) sg2[t] = g2[t];
        __syncthreads();
        if (t < 128) {
            float s0 = d1[t], s1 = 0.f, s2 = 0.f, s3 = 0.f;
            for (int r = 0; r < KTOT; r += 4) {
                s0 = fmaf(sg2[(r    ) & 127], D1[(size_t)(r    ) * 128 + t], s0);
                s1 = fmaf(sg2[(r + 1) & 127], D1[(size_t)(r + 1) * 128 + t], s1);
                s2 = fmaf(sg2[(r + 2) & 127], D1[(size_t)(r + 2) * 128 + t], s2);
                s3 = fmaf(sg2[(r + 3) & 127], D1[(size_t)(r + 3) * 128 + t], s3);
            }
            g_c0[t] = s0 + s1 + s2 + s3;
        }
        return;
    }

    // E block: i = bx>>2 selects node, k0 = (bx&3)*32 selects 32 k-rows
    extern __shared__ float sm0[];
    float* sG2t = sm0;              // [m=128][kl=32] stride 36
    float* sD1  = sG2t + 128 * 36;  // [m=128][h=128] stride 132

    const int i  = bx >> 2;
    const int k0 = (bx & 3) * 32;

    for (int idx = t; idx < 32 * 128; idx += 256) {
        int kl = idx >> 7, m = idx & 127;
        sG2t[m * 36 + kl] = G2[(size_t)(k0 + kl) * 128 + m];
    }
    for (int idx = t; idx < 128 * 128; idx += 256) {
        int m = idx >> 7, h = idx & 127;
        sD1[m * 132 + h] = D1[(size_t)(i * 128 + m) * 128 + h];
    }
    __syncthreads();

    const int tk = t >> 5;   // 0..7  -> kl = tk*4 .. +3
    const int th = t & 31;   // 0..31 -> h  = th*4 .. +3
    float acc[4][4];
#pragma unroll
    for (int p = 0; p < 4; p++)
#pragma unroll
        for (int q = 0; q < 4; q++) acc[p][q] = 0.f;

#pragma unroll 4
    for (int m = 0; m < 128; m++) {
        float4 a = *(const float4*)&sG2t[m * 36 + tk * 4];
        float4 b = *(const float4*)&sD1[m * 132 + th * 4];
        float av[4] = {a.x, a.y, a.z, a.w};
        float bv[4] = {b.x, b.y, b.z, b.w};
#pragma unroll
        for (int p = 0; p < 4; p++)
#pragma unroll
            for (int q = 0; q < 4; q++)
                acc[p][q] = fmaf(av[p], bv[q], acc[p][q]);
    }

#pragma unroll
    for (int p = 0; p < 4; p++) {
        int k = k0 + tk * 4 + p;
        float4 v = make_float4(acc[p][0], acc[p][1], acc[p][2], acc[p][3]);
        *(float4*)&g_E[((size_t)(i * 128 + k)) * 128 + th * 4] = v;
    }
}

// ---------------------------------------------------------------------------
// Kernel 1: per-batch node transform + adjacency + aggregation + G1 layer.
// 512 threads = 16 warps, one warp per batch. grid = 8192/16 = 512.
// Writes Y[b][i*128+h] = relu(x_i @ G1 + g1)[h]
// ---------------------------------------------------------------------------
#define K1_WARPS 16
#define WBUF_STRIDE 2084   // nd(660) + uu(660) + vv(660) + adj(104)

__global__ void __launch_bounds__(512, 1) gnn_kernel(
    const float* __restrict__ hidden,
    const float* __restrict__ W1, const float* __restrict__ b1,
    const float* __restrict__ W2, const float* __restrict__ b2,
    const float* __restrict__ G1, const float* __restrict__ g1)
{
    extern __shared__ float sm[];
    float* sW1   = sm;            // 8192  [f(128)][c(64)]
    float* sG1   = sW1 + 8192;    // 8192  [f(64)][h(128)]
    float* sb1   = sG1 + 8192;    // 64
    float* sW2   = sb1 + 64;      // 64
    float* sg1   = sW2 + 64;      // 128
    float* smisc = sg1 + 128;     // [0] = b2, padded to 16
    float* warpbuf = smisc + 16;

    const int tid = threadIdx.x;
    for (int idx = tid; idx < 8192; idx += 512) sW1[idx] = W1[idx];
    for (int idx = tid; idx < 8192; idx += 512) sG1[idx] = G1[idx];
    if (tid < 64)                      sb1[tid]        = b1[tid];
    else if (tid < 128)                sW2[tid - 64]   = W2[tid - 64];
    else if (tid < 256)                sg1[tid - 128]  = g1[tid - 128];
    else if (tid == 256)               smisc[0]        = b2[0];
    __syncthreads();

    const int wid  = tid >> 5;
    const int lane = tid & 31;
    const int b    = blockIdx.x * K1_WARPS + wid;

    float* nd  = warpbuf + wid * WBUF_STRIDE;  // [10][66]
    float* uu  = nd + 660;                     // [10][66]  (u + b1), later x
    float* vv  = uu + 660;                     // [10][66]
    float* adj = vv + 660;                     // [100]

    // ---- load node: nd[n][f] = hidden[n][b][f] ----
    {
        const float* hb = hidden + (size_t)b * FEAT;
#pragma unroll
        for (int n = 0; n < NCLS; n++) {
            float2 v = *(const float2*)&hb[(size_t)n * BATCH * FEAT + 2 * lane];
            *(float2*)&nd[n * 66 + 2 * lane] = v;
        }
    }
    __syncwarp();

    // ---- u = node @ W1[:64] + b1,  v = node @ W1[64:] ----
    {
        float ua[NCLS], ub[NCLS], va[NCLS], vb[NCLS];
#pragma unroll
        for (int i = 0; i < NCLS; i++) { ua[i] = 0.f; ub[i] = 0.f; va[i] = 0.f; vb[i] = 0.f; }
        const int c0 = 2 * lane;
#pragma unroll 8
        for (int f = 0; f < 64; f++) {
            float2 wu = *(const float2*)&sW1[f * 64 + c0];
            float2 wv = *(const float2*)&sW1[(64 + f) * 64 + c0];
#pragma unroll
            for (int i = 0; i < NCLS; i++) {
                float nf = nd[i * 66 + f];
                ua[i] = fmaf(nf, wu.x, ua[i]);
                ub[i] = fmaf(nf, wu.y, ub[i]);
                va[i] = fmaf(nf, wv.x, va[i]);
                vb[i] = fmaf(nf, wv.y, vb[i]);
            }
        }
        float b1a = sb1[c0], b1b = sb1[c0 + 1];
#pragma unroll
        for (int i = 0; i < NCLS; i++) {
            float2 u2 = make_float2(ua[i] + b1a, ub[i] + b1b);
            *(float2*)&uu[i * 66 + c0] = u2;
            float2 v2 = make_float2(va[i], vb[i]);
            *(float2*)&vv[i * 66 + c0] = v2;
        }
    }
    __syncwarp();

    // ---- adjacency: adj[i][j] = sigmoid(relu(u_i+v_j) . W2 + b2), diag = 1 ----
    {
        const float b2v = smisc[0];
        for (int p = lane; p < 100; p += 32) {
            int i = p / 10, j = p - i * 10;
            float s = b2v;
#pragma unroll 8
            for (int c2 = 0; c2 < 32; c2++) {
                float2 u2 = *(const float2*)&uu[i * 66 + 2 * c2];
                float2 v2 = *(const float2*)&vv[j * 66 + 2 * c2];
                s = fmaf(fmaxf(u2.x + v2.x, 0.f), sW2[2 * c2],     s);
                s = fmaf(fmaxf(u2.y + v2.y, 0.f), sW2[2 * c2 + 1], s);
            }
            adj[p] = (i == j) ? 1.0f : (1.0f / (1.0f + expf(-s)));
        }
    }
    __syncwarp();

    // ---- x = node + adj @ node  (store into uu) ----
    {
        const int f0 = 2 * lane;
        float xa[NCLS], xb[NCLS];
#pragma unroll
        for (int i = 0; i < NCLS; i++) {
            float2 n2 = *(const float2*)&nd[i * 66 + f0];
            xa[i] = n2.x; xb[i] = n2.y;
        }
#pragma unroll
        for (int j = 0; j < NCLS; j++) {
            float2 nj = *(const float2*)&nd[j * 66 + f0];
#pragma unroll
            for (int i = 0; i < NCLS; i++) {
                float a = adj[i * 10 + j];
                xa[i] = fmaf(a, nj.x, xa[i]);
                xb[i] = fmaf(a, nj.y, xb[i]);
            }
        }
#pragma unroll
        for (int i = 0; i < NCLS; i++) {
            float2 x2 = make_float2(xa[i], xb[i]);
            *(float2*)&uu[i * 66 + f0] = x2;
        }
    }
    __syncwarp();

    // ---- y_i = relu(x_i @ G1 + g1) -> global Y ----
    {
        float* Yrow = g_Y + (size_t)b * KTOT;
        const int h0 = 4 * lane;
        float y0[NCLS], y1[NCLS], y2[NCLS], y3[NCLS];
        const float gv0 = sg1[h0], gv1 = sg1[h0 + 1], gv2 = sg1[h0 + 2], gv3 = sg1[h0 + 3];
#pragma unroll
        for (int i = 0; i < NCLS; i++) { y0[i] = gv0; y1[i] = gv1; y2[i] = gv2; y3[i] = gv3; }
#pragma unroll 4
        for (int f = 0; f < 64; f++) {
            float4 w = *(const float4*)&sG1[f * 128 + h0];
#pragma unroll
            for (int i = 0; i < NCLS; i++) {
                float xv = uu[i * 66 + f];
                y0[i] = fmaf(xv, w.x, y0[i]);
                y1[i] = fmaf(xv, w.y, y1[i]);
                y2[i] = fmaf(xv, w.z, y2[i]);
                y3[i] = fmaf(xv, w.w, y3[i]);
            }
        }
#pragma unroll
        for (int i = 0; i < NCLS; i++) {
            float4 o = make_float4(fmaxf(y0[i], 0.f), fmaxf(y1[i], 0.f),
                                   fmaxf(y2[i], 0.f), fmaxf(y3[i], 0.f));
            *(float4*)&Yrow[i * 128 + h0] = o;
        }
    }
}

// ---------------------------------------------------------------------------
// Kernel 2: out[b] = relu(Y[b] @ E + c0) . D2 + d2
// M=8192, K=1280, N=128. M_TILE=64, 256 threads, thread tile 8x4.
// grid = 128
// ---------------------------------------------------------------------------
__global__ void __launch_bounds__(256, 1) dec_kernel(
    const float* __restrict__ D2, const float* __restrict__ d2,
    float* __restrict__ out)
{
    __shared__ float At[32][68];    // [kk][row], transposed A tile
    __shared__ float Bt[32][132];   // [kk][n]

    const int t  = threadIdx.x;
    const int m0 = blockIdx.x * 64;
    const int tr = t >> 5;          // 0..7  -> rows tr*8..+7 (warp = one tr)
    const int tc = t & 31;          // cols tc*4..+3

    float acc[8][4];
#pragma unroll
    for (int p = 0; p < 8; p++)
#pragma unroll
        for (int q = 0; q < 4; q++) acc[p][q] = 0.f;

    const int lrow = t >> 2;          // 0..63   (A loader)
    const int lk   = (t & 3) * 8;
    const int bkk  = t >> 3;          // 0..31   (B loader)
    const int bn   = (t & 7) * 16;

    for (int k0 = 0; k0 < KTOT; k0 += 32) {
        // A tile: Y[(m0+lrow)][k0+lk .. +7], transposed into At
        const float* yp = g_Y + (size_t)(m0 + lrow) * KTOT + k0 + lk;
        float4 a0 = *(const float4*)yp;
        float4 a1 = *(const float4*)(yp + 4);
        At[lk + 0][lrow] = a0.x; At[lk + 1][lrow] = a0.y;
        At[lk + 2][lrow] = a0.z; At[lk + 3][lrow] = a0.w;
        At[lk + 4][lrow] = a1.x; At[lk + 5][lrow] = a1.y;
        At[lk + 6][lrow] = a1.z; At[lk + 7][lrow] = a1.w;
        // B tile: E[(k0+bkk)][bn .. +15]
        const float* ep = g_E + (size_t)(k0 + bkk) * 128 + bn;
        float4 e0 = *(const float4*)ep;
        float4 e1 = *(const float4*)(ep + 4);
        float4 e2 = *(const float4*)(ep + 8);
        float4 e3 = *(const float4*)(ep + 12);
        *(float4*)&Bt[bkk][bn + 0]  = e0;
        *(float4*)&Bt[bkk][bn + 4]  = e1;
        *(float4*)&Bt[bkk][bn + 8]  = e2;
        *(float4*)&Bt[bkk][bn + 12] = e3;
        __syncthreads();

#pragma unroll
        for (int kk = 0; kk < 32; kk++) {
            float4 a_0 = *(const float4*)&At[kk][tr * 8];
            float4 a_1 = *(const float4*)&At[kk][tr * 8 + 4];
            float4 bb  = *(const float4*)&Bt[kk][tc * 4];
            float ar[8] = {a_0.x, a_0.y, a_0.z, a_0.w, a_1.x, a_1.y, a_1.z, a_1.w};
            float br[4] = {bb.x, bb.y, bb.z, bb.w};
#pragma unroll
            for (int p = 0; p < 8; p++)
#pragma unroll
                for (int q = 0; q < 4; q++)
                    acc[p][q] = fmaf(ar[p], br[q], acc[p][q]);
        }
        __syncthreads();
    }

    // epilogue: relu(acc + c0) . D2 segment, warp-reduce over tc, add d2
    float c0v[4], d2v[4];
#pragma unroll
    for (int q = 0; q < 4; q++) {
        c0v[q] = g_c0[tc * 4 + q];
        d2v[q] = D2[tc * 4 + q];
    }
    const float d2s = d2[0];
#pragma unroll
    for (int p = 0; p < 8; p++) {
        float s = 0.f;
#pragma unroll
        for (int q = 0; q < 4; q++)
            s = fmaf(fmaxf(acc[p][q] + c0v[q], 0.f), d2v[q], s);
#pragma unroll
        for (int o = 16; o; o >>= 1)
            s += __shfl_xor_sync(0xffffffffu, s, o);
        if (tc == 0)
            out[m0 + tr * 8 + p] = s + d2s;
    }
}

// ---------------------------------------------------------------------------
extern "C" void kernel_launch(void* const* d_in, const int* in_sizes, int n_in,
                              void* d_out, int out_size) {
    // metadata order: logits_list(0, unused), hidden(1), W1(2), b1(3), W2(4),
    // b2(5), G1(6), g1(7), G2(8), g2(9), D1(10), d1(11), D2(12), d2(13)
    const float* hidden = (const float*)d_in[1];
    const float* W1 = (const float*)d_in[2];
    const float* b1 = (const float*)d_in[3];
    const float* W2 = (const float*)d_in[4];
    const float* b2 = (const float*)d_in[5];
    const float* G1 = (const float*)d_in[6];
    const float* g1 = (const float*)d_in[7];
    const float* G2 = (const float*)d_in[8];
    const float* g2 = (const float*)d_in[9];
    const float* D1 = (const float*)d_in[10];
    const float* d1 = (const float*)d_in[11];
    const float* D2 = (const float*)d_in[12];
    const float* d2 = (const float*)d_in[13];
    float* out = (float*)d_out;

    const int SMEM0 = (128 * 36 + 128 * 132) * 4;                              // 86016 B
    const int SMEM1 = (8192 + 8192 + 64 + 64 + 128 + 16 + K1_WARPS * WBUF_STRIDE) * 4; // 200000 B

    cudaFuncSetAttribute(prep_kernel, cudaFuncAttributeMaxDynamicSharedMemorySize, SMEM0);
    cudaFuncSetAttribute(gnn_kernel,  cudaFuncAttributeMaxDynamicSharedMemorySize, SMEM1);

    prep_kernel<<<41, 256, SMEM0>>>(G2, g2, D1, d1);
    gnn_kernel<<<BATCH / K1_WARPS, 512, SMEM1>>>(hidden, W1, b1, W2, b2, G1, g1);
    dec_kernel<<<BATCH / 64, 256>>>(D2, d2, out);
}

// round 3
// speedup vs baseline: 1.2809x; 1.2809x over previous
#include <cuda_runtime.h>
#include <math.h>
#include <stdint.h>

#define BATCH 8192
#define NCLS  10
#define FEAT  64
#define HID   128
#define KTOT  (NCLS * HID)   // 1280

// Scratch (static device arrays: allocation-free per harness rules)
__device__ float g_Y[(size_t)BATCH * KTOT];   // relu(x @ G1 + g1), [8192][1280]
__device__ float g_E[NCLS * HID * HID];       // E[i][k][h] = sum_h' G2[k][h'] D1[i*128+h'][h]
__device__ float g_c0p[NCLS * HID];           // partial c0 per node

// ---------------------------------------------------------------------------
// Kernel 0: precompute E and c0 partials. grid = 170 x 128 threads.
// ---------------------------------------------------------------------------
__global__ void __launch_bounds__(128) prep_kernel(
    const float* __restrict__ G2, const float* __restrict__ g2,
    const float* __restrict__ D1)
{
    const int bx = blockIdx.x;
    const int t  = threadIdx.x;

    if (bx >= 160) {
        const int ii = bx - 160;
        const float* dp = D1 + (size_t)(ii * 128) * 128 + t;
        float s0 = 0.f, s1 = 0.f, s2 = 0.f, s3 = 0.f;
#pragma unroll 4
        for (int r = 0; r < 128; r += 4) {
            s0 = fmaf(g2[r    ], dp[(size_t)(r    ) * 128], s0);
            s1 = fmaf(g2[r + 1], dp[(size_t)(r + 1) * 128], s1);
            s2 = fmaf(g2[r + 2], dp[(size_t)(r + 2) * 128], s2);
            s3 = fmaf(g2[r + 3], dp[(size_t)(r + 3) * 128], s3);
        }
        g_c0p[ii * 128 + t] = (s0 + s1) + (s2 + s3);
        return;
    }

    __shared__ float sG2[8 * 128];
    const int i  = bx >> 4;
    const int k0 = (bx & 15) * 8;

    for (int r = t; r < 8 * 128; r += 128) {
        int kk = r >> 7, hp = r & 127;
        sG2[kk * 128 + hp] = G2[(size_t)(k0 + kk) * 128 + hp];
    }
    __syncthreads();

    float acc[8];
#pragma unroll
    for (int kk = 0; kk < 8; kk++) acc[kk] = 0.f;

    const float* dp = D1 + (size_t)(i * 128) * 128 + t;
#pragma unroll 4
    for (int hp = 0; hp < 128; hp++) {
        float dv = dp[(size_t)hp * 128];
#pragma unroll
        for (int kk = 0; kk < 8; kk++)
            acc[kk] = fmaf(sG2[kk * 128 + hp], dv, acc[kk]);
    }
#pragma unroll
    for (int kk = 0; kk < 8; kk++)
        g_E[(size_t)(i * 128 + k0 + kk) * 128 + t] = acc[kk];
}

// ---------------------------------------------------------------------------
// Kernel 1: per-batch node transform + adjacency + aggregation + G1 layer.
// ---------------------------------------------------------------------------
#define K1_WARPS 16
#define WBUF_STRIDE 2084

__global__ void __launch_bounds__(512, 1) gnn_kernel(
    const float* __restrict__ hidden,
    const float* __restrict__ W1, const float* __restrict__ b1,
    const float* __restrict__ W2, const float* __restrict__ b2,
    const float* __restrict__ G1, const float* __restrict__ g1)
{
    extern __shared__ float sm[];
    float* sW1   = sm;
    float* sG1   = sW1 + 8192;
    float* sb1   = sG1 + 8192;
    float* sW2   = sb1 + 64;
    float* sg1   = sW2 + 64;
    float* smisc = sg1 + 128;
    float* warpbuf = smisc + 16;

    const int tid = threadIdx.x;
    for (int idx = tid; idx < 8192; idx += 512) sW1[idx] = W1[idx];
    for (int idx = tid; idx < 8192; idx += 512) sG1[idx] = G1[idx];
    if (tid < 64)                      sb1[tid]        = b1[tid];
    else if (tid < 128)                sW2[tid - 64]   = W2[tid - 64];
    else if (tid < 256)                sg1[tid - 128]  = g1[tid - 128];
    else if (tid == 256)               smisc[0]        = b2[0];
    __syncthreads();

    const int wid  = tid >> 5;
    const int lane = tid & 31;
    const int b    = blockIdx.x * K1_WARPS + wid;

    float* nd  = warpbuf + wid * WBUF_STRIDE;
    float* uu  = nd + 660;
    float* vv  = uu + 660;
    float* adj = vv + 660;

    {
        const float* hb = hidden + (size_t)b * FEAT;
#pragma unroll
        for (int n = 0; n < NCLS; n++) {
            float2 v = *(const float2*)&hb[(size_t)n * BATCH * FEAT + 2 * lane];
            *(float2*)&nd[n * 66 + 2 * lane] = v;
        }
    }
    __syncwarp();

    {
        float ua[NCLS], ub[NCLS], va[NCLS], vb[NCLS];
#pragma unroll
        for (int i = 0; i < NCLS; i++) { ua[i] = 0.f; ub[i] = 0.f; va[i] = 0.f; vb[i] = 0.f; }
        const int c0 = 2 * lane;
#pragma unroll 8
        for (int f = 0; f < 64; f++) {
            float2 wu = *(const float2*)&sW1[f * 64 + c0];
            float2 wv = *(const float2*)&sW1[(64 + f) * 64 + c0];
#pragma unroll
            for (int i = 0; i < NCLS; i++) {
                float nf = nd[i * 66 + f];
                ua[i] = fmaf(nf, wu.x, ua[i]);
                ub[i] = fmaf(nf, wu.y, ub[i]);
                va[i] = fmaf(nf, wv.x, va[i]);
                vb[i] = fmaf(nf, wv.y, vb[i]);
            }
        }
        float b1a = sb1[c0], b1b = sb1[c0 + 1];
#pragma unroll
        for (int i = 0; i < NCLS; i++) {
            float2 u2 = make_float2(ua[i] + b1a, ub[i] + b1b);
            *(float2*)&uu[i * 66 + c0] = u2;
            float2 v2 = make_float2(va[i], vb[i]);
            *(float2*)&vv[i * 66 + c0] = v2;
        }
    }
    __syncwarp();

    {
        const float b2v = smisc[0];
        for (int p = lane; p < 100; p += 32) {
            int i = p / 10, j = p - i * 10;
            float s = b2v;
#pragma unroll 8
            for (int c2 = 0; c2 < 32; c2++) {
                float2 u2 = *(const float2*)&uu[i * 66 + 2 * c2];
                float2 v2 = *(const float2*)&vv[j * 66 + 2 * c2];
                s = fmaf(fmaxf(u2.x + v2.x, 0.f), sW2[2 * c2],     s);
                s = fmaf(fmaxf(u2.y + v2.y, 0.f), sW2[2 * c2 + 1], s);
            }
            adj[p] = (i == j) ? 1.0f : (1.0f / (1.0f + expf(-s)));
        }
    }
    __syncwarp();

    {
        const int f0 = 2 * lane;
        float xa[NCLS], xb[NCLS];
#pragma unroll
        for (int i = 0; i < NCLS; i++) {
            float2 n2 = *(const float2*)&nd[i * 66 + f0];
            xa[i] = n2.x; xb[i] = n2.y;
        }
#pragma unroll
        for (int j = 0; j < NCLS; j++) {
            float2 nj = *(const float2*)&nd[j * 66 + f0];
#pragma unroll
            for (int i = 0; i < NCLS; i++) {
                float a = adj[i * 10 + j];
                xa[i] = fmaf(a, nj.x, xa[i]);
                xb[i] = fmaf(a, nj.y, xb[i]);
            }
        }
#pragma unroll
        for (int i = 0; i < NCLS; i++) {
            float2 x2 = make_float2(xa[i], xb[i]);
            *(float2*)&uu[i * 66 + f0] = x2;
        }
    }
    __syncwarp();

    {
        float* Yrow = g_Y + (size_t)b * KTOT;
        const int h0 = 4 * lane;
        float y0[NCLS], y1[NCLS], y2[NCLS], y3[NCLS];
        const float gv0 = sg1[h0], gv1 = sg1[h0 + 1], gv2 = sg1[h0 + 2], gv3 = sg1[h0 + 3];
#pragma unroll
        for (int i = 0; i < NCLS; i++) { y0[i] = gv0; y1[i] = gv1; y2[i] = gv2; y3[i] = gv3; }
#pragma unroll 4
        for (int f = 0; f < 64; f++) {
            float4 w = *(const float4*)&sG1[f * 128 + h0];
#pragma unroll
            for (int i = 0; i < NCLS; i++) {
                float xv = uu[i * 66 + f];
                y0[i] = fmaf(xv, w.x, y0[i]);
                y1[i] = fmaf(xv, w.y, y1[i]);
                y2[i] = fmaf(xv, w.z, y2[i]);
                y3[i] = fmaf(xv, w.w, y3[i]);
            }
        }
#pragma unroll
        for (int i = 0; i < NCLS; i++) {
            float4 o = make_float4(fmaxf(y0[i], 0.f), fmaxf(y1[i], 0.f),
                                   fmaxf(y2[i], 0.f), fmaxf(y3[i], 0.f));
            *(float4*)&Yrow[i * 128 + h0] = o;
        }
    }
}

// ---------------------------------------------------------------------------
// Kernel 2: out[b] = relu(Y[b] @ E + c0) . D2 + d2, via tf32 mma.sync.
// M=8192 (tile 64), N=128, K=1280 (chunk 32). grid=128, 256 threads (8 warps).
// ---------------------------------------------------------------------------
__device__ __forceinline__ uint32_t f2tf32(float x) {
    uint32_t r;
    asm("cvt.rna.tf32.f32 %0, %1;" : "=r"(r) : "f"(x));
    return r;
}

#define AS_STRIDE 36    // k-pad: banks 4g+tg distinct
#define BS_STRIDE 136   // n-pad: 136 mod 32 = 8 -> banks n0+g+8tg all distinct

__global__ void __launch_bounds__(256, 1) dec_kernel(
    const float* __restrict__ d1, const float* __restrict__ D2,
    const float* __restrict__ d2, float* __restrict__ out)
{
    __shared__ uint32_t As[64 * AS_STRIDE];   // [m=64][k=32], stride 36
    __shared__ uint32_t Bs[32 * BS_STRIDE];   // [k=32][n=128], stride 136
    __shared__ float rowsum[4][64];

    const int t    = threadIdx.x;
    const int m0   = blockIdx.x * 64;
    const int wid  = t >> 5;
    const int lane = t & 31;
    const int wm   = wid >> 2;        // 0..1 -> rows wm*32
    const int wn   = wid & 3;         // 0..3 -> cols wn*32
    const int g    = lane >> 2;       // groupID
    const int tg   = lane & 3;        // threadID_in_group

    // loader indices
    const int arow = t >> 2;          // 0..63
    const int akc  = (t & 3) * 8;     // 0,8,16,24
    const int bkk  = t >> 3;          // 0..31
    const int bn   = (t & 7) * 16;    // 0..112

    float c[2][4][4];
#pragma unroll
    for (int mf = 0; mf < 2; mf++)
#pragma unroll
        for (int nf = 0; nf < 4; nf++)
#pragma unroll
            for (int q = 0; q < 4; q++) c[mf][nf][q] = 0.f;

    for (int k0 = 0; k0 < KTOT; k0 += 32) {
        // A tile: Y[m0+arow][k0+akc .. +7]
        {
            const float* yp = g_Y + (size_t)(m0 + arow) * KTOT + k0 + akc;
            float4 a0 = *(const float4*)yp;
            float4 a1 = *(const float4*)(yp + 4);
            uint32_t* d = &As[arow * AS_STRIDE + akc];
            d[0] = f2tf32(a0.x); d[1] = f2tf32(a0.y); d[2] = f2tf32(a0.z); d[3] = f2tf32(a0.w);
            d[4] = f2tf32(a1.x); d[5] = f2tf32(a1.y); d[6] = f2tf32(a1.z); d[7] = f2tf32(a1.w);
        }
        // B tile: E[k0+bkk][bn .. +15]
        {
            const float* ep = g_E + (size_t)(k0 + bkk) * 128 + bn;
            uint32_t* d = &Bs[bkk * BS_STRIDE + bn];
#pragma unroll
            for (int q4 = 0; q4 < 4; q4++) {
                float4 e = *(const float4*)(ep + q4 * 4);
                d[q4 * 4 + 0] = f2tf32(e.x); d[q4 * 4 + 1] = f2tf32(e.y);
                d[q4 * 4 + 2] = f2tf32(e.z); d[q4 * 4 + 3] = f2tf32(e.w);
            }
        }
        __syncthreads();

#pragma unroll
        for (int kk = 0; kk < 32; kk += 8) {
            uint32_t a[2][4], bfr[4][2];
#pragma unroll
            for (int mf = 0; mf < 2; mf++) {
                const uint32_t* ap = &As[(wm * 32 + mf * 16 + g) * AS_STRIDE + kk + tg];
                a[mf][0] = ap[0];
                a[mf][1] = ap[8 * AS_STRIDE];
                a[mf][2] = ap[4];
                a[mf][3] = ap[8 * AS_STRIDE + 4];
            }
#pragma unroll
            for (int nf = 0; nf < 4; nf++) {
                const uint32_t* bp = &Bs[(kk + tg) * BS_STRIDE + wn * 32 + nf * 8 + g];
                bfr[nf][0] = bp[0];
                bfr[nf][1] = bp[4 * BS_STRIDE];
            }
#pragma unroll
            for (int mf = 0; mf < 2; mf++)
#pragma unroll
                for (int nf = 0; nf < 4; nf++) {
                    asm volatile(
                        "mma.sync.aligned.m16n8k8.row.col.f32.tf32.tf32.f32 "
                        "{%0,%1,%2,%3}, {%4,%5,%6,%7}, {%8,%9}, {%0,%1,%2,%3};"
                        : "+f"(c[mf][nf][0]), "+f"(c[mf][nf][1]),
                          "+f"(c[mf][nf][2]), "+f"(c[mf][nf][3])
                        : "r"(a[mf][0]), "r"(a[mf][1]), "r"(a[mf][2]), "r"(a[mf][3]),
                          "r"(bfr[nf][0]), "r"(bfr[nf][1]));
                }
        }
        __syncthreads();
    }

    // epilogue: s[row] = sum_col relu(c + c0[col]) * D2[col]; out = s + d2
    float c0v[4][2], d2v[4][2];
#pragma unroll
    for (int nf = 0; nf < 4; nf++) {
#pragma unroll
        for (int j = 0; j < 2; j++) {
            int col = wn * 32 + nf * 8 + tg * 2 + j;
            float base = d1[col];
#pragma unroll
            for (int ii = 0; ii < NCLS; ii++) base += g_c0p[ii * 128 + col];
            c0v[nf][j] = base;
            d2v[nf][j] = D2[col];
        }
    }

#pragma unroll
    for (int mf = 0; mf < 2; mf++) {
        float p0 = 0.f, p1 = 0.f;
#pragma unroll
        for (int nf = 0; nf < 4; nf++) {
            p0 = fmaf(fmaxf(c[mf][nf][0] + c0v[nf][0], 0.f), d2v[nf][0], p0);
            p0 = fmaf(fmaxf(c[mf][nf][1] + c0v[nf][1], 0.f), d2v[nf][1], p0);
            p1 = fmaf(fmaxf(c[mf][nf][2] + c0v[nf][0], 0.f), d2v[nf][0], p1);
            p1 = fmaf(fmaxf(c[mf][nf][3] + c0v[nf][1], 0.f), d2v[nf][1], p1);
        }
        p0 += __shfl_xor_sync(0xffffffffu, p0, 1);
        p0 += __shfl_xor_sync(0xffffffffu, p0, 2);
        p1 += __shfl_xor_sync(0xffffffffu, p1, 1);
        p1 += __shfl_xor_sync(0xffffffffu, p1, 2);
        if (tg == 0) {
            rowsum[wn][wm * 32 + mf * 16 + g]     = p0;
            rowsum[wn][wm * 32 + mf * 16 + g + 8] = p1;
        }
    }
    __syncthreads();

    if (t < 64) {
        float s = rowsum[0][t] + rowsum[1][t] + rowsum[2][t] + rowsum[3][t];
        out[m0 + t] = s + d2[0];
    }
}

// ---------------------------------------------------------------------------
extern "C" void kernel_launch(void* const* d_in, const int* in_sizes, int n_in,
                              void* d_out, int out_size) {
    const float* hidden = (const float*)d_in[1];
    const float* W1 = (const float*)d_in[2];
    const float* b1 = (const float*)d_in[3];
    const float* W2 = (const float*)d_in[4];
    const float* b2 = (const float*)d_in[5];
    const float* G1 = (const float*)d_in[6];
    const float* g1 = (const float*)d_in[7];
    const float* G2 = (const float*)d_in[8];
    const float* g2 = (const float*)d_in[9];
    const float* D1 = (const float*)d_in[10];
    const float* d1 = (const float*)d_in[11];
    const float* D2 = (const float*)d_in[12];
    const float* d2 = (const float*)d_in[13];
    float* out = (float*)d_out;

    const int SMEM1 = (8192 + 8192 + 64 + 64 + 128 + 16 + K1_WARPS * WBUF_STRIDE) * 4;
    cudaFuncSetAttribute(gnn_kernel, cudaFuncAttributeMaxDynamicSharedMemorySize, SMEM1);

    prep_kernel<<<170, 128>>>(G2, g2, D1);
    gnn_kernel<<<BATCH / K1_WARPS, 512, SMEM1>>>(hidden, W1, b1, W2, b2, G1, g1);
    dec_kernel<<<BATCH / 64, 256>>>(d1, D2, d2, out);
}

// round 4
// speedup vs baseline: 1.3892x; 1.0845x over previous
#include <cuda_runtime.h>
#include <math.h>
#include <stdint.h>

#define BATCH 8192
#define NCLS  10
#define FEAT  64
#define HID   128
#define KTOT  (NCLS * HID)   // 1280

// Scratch (tf32 bit patterns stored as uint32 where noted)
__device__ uint32_t g_Y[(size_t)BATCH * KTOT];  // tf32 relu(x@G1+g1), layout [i][b][h]
__device__ uint32_t g_E[NCLS * HID * HID];      // tf32 E[i][k][h]
__device__ float    g_c0p[NCLS * HID];          // f32 partial c0 per node

__device__ __forceinline__ uint32_t f2tf32(float x) {
    uint32_t r;
    asm("cvt.rna.tf32.f32 %0, %1;" : "=r"(r) : "f"(x));
    return r;
}

#define MMA_TF32(C, A0, A1, A2, A3, B0, B1)                                  \
    asm volatile(                                                            \
        "mma.sync.aligned.m16n8k8.row.col.f32.tf32.tf32.f32 "               \
        "{%0,%1,%2,%3}, {%4,%5,%6,%7}, {%8,%9}, {%0,%1,%2,%3};"             \
        : "+f"((C)[0]), "+f"((C)[1]), "+f"((C)[2]), "+f"((C)[3])            \
        : "r"(A0), "r"(A1), "r"(A2), "r"(A3), "r"(B0), "r"(B1))

// ---------------------------------------------------------------------------
// Kernel 0: precompute E (tf32) and c0 partials. grid = 330 x 128 threads.
//   bx < 320 : i = bx/32, k0 = (bx%32)*4 -> E rows [i][k0..k0+3][*]
//   bx >= 320: ii = bx-320 -> g_c0p[ii][*]
// ---------------------------------------------------------------------------
__global__ void __launch_bounds__(128) prep_kernel(
    const float* __restrict__ G2, const float* __restrict__ g2,
    const float* __restrict__ D1)
{
    const int bx = blockIdx.x;
    const int t  = threadIdx.x;

    if (bx >= 320) {
        const int ii = bx - 320;
        const float* dp = D1 + (size_t)(ii * 128) * 128 + t;
        float s = 0.f;
        for (int r0 = 0; r0 < 128; r0 += 8) {
            float dv[8];
#pragma unroll
            for (int j = 0; j < 8; j++) dv[j] = dp[(size_t)(r0 + j) * 128];
#pragma unroll
            for (int j = 0; j < 8; j++) s = fmaf(g2[r0 + j], dv[j], s);
        }
        g_c0p[ii * 128 + t] = s;
        return;
    }

    __shared__ float sG2[4 * 128];
    const int i  = bx >> 5;
    const int k0 = (bx & 31) * 4;

    for (int r = t; r < 512; r += 128)
        sG2[r] = G2[(size_t)(k0 + (r >> 7)) * 128 + (r & 127)];
    __syncthreads();

    float acc[4] = {0.f, 0.f, 0.f, 0.f};
    const float* dp = D1 + (size_t)(i * 128) * 128 + t;
    for (int h0 = 0; h0 < 128; h0 += 8) {
        float dv[8];
#pragma unroll
        for (int j = 0; j < 8; j++) dv[j] = dp[(size_t)(h0 + j) * 128];
#pragma unroll
        for (int j = 0; j < 8; j++)
#pragma unroll
            for (int kk = 0; kk < 4; kk++)
                acc[kk] = fmaf(sG2[kk * 128 + h0 + j], dv[j], acc[kk]);
    }
#pragma unroll
    for (int kk = 0; kk < 4; kk++)
        g_E[(size_t)(i * 128 + k0 + kk) * 128 + t] = f2tf32(acc[kk]);
}

// ---------------------------------------------------------------------------
// Kernel 1: per-batch GNN front-end. One warp per batch, 16 warps/block.
// u/v and G1 stages use tf32 mma (M=16 padded over 10 nodes, rows >=10
// handled by predicated zero A-frags). adjacency/aggregation stay scalar.
// ---------------------------------------------------------------------------
#define K1_WARPS 16
#define ND_STR 68                    // row stride for nd/uu/vv (68 mod 32 = 4)
#define WBUF_STRIDE 2144             // nd 680 + uu 680 + vv 680 + adj 104

__global__ void __launch_bounds__(512, 1) gnn_kernel(
    const float* __restrict__ hidden,
    const float* __restrict__ W1, const float* __restrict__ b1,
    const float* __restrict__ W2, const float* __restrict__ b2,
    const float* __restrict__ G1, const float* __restrict__ g1)
{
    extern __shared__ float sm[];
    uint32_t* sW1 = (uint32_t*)sm;          // [f=128][c=64] pad 68  (tf32)
    uint32_t* sG1 = sW1 + 128 * 68;         // [f=64][h=128] pad 132 (tf32)
    float* sb1   = (float*)(sG1 + 64 * 132);// 64
    float* sW2   = sb1 + 64;                // 64
    float* sg1   = sW2 + 64;                // 128
    float* smisc = sg1 + 128;               // 16
    float* warpbuf = smisc + 16;

    const int tid = threadIdx.x;
    for (int idx = tid; idx < 8192; idx += 512) {
        int f = idx >> 6, c = idx & 63;
        sW1[f * 68 + c] = f2tf32(W1[idx]);
    }
    for (int idx = tid; idx < 8192; idx += 512) {
        int f = idx >> 7, h = idx & 127;
        sG1[f * 132 + h] = f2tf32(G1[idx]);
    }
    if (tid < 64)        sb1[tid]        = b1[tid];
    else if (tid < 128)  sW2[tid - 64]   = W2[tid - 64];
    else if (tid < 256)  sg1[tid - 128]  = g1[tid - 128];
    else if (tid == 256) smisc[0]        = b2[0];
    __syncthreads();

    const int wid  = tid >> 5;
    const int lane = tid & 31;
    const int g    = lane >> 2;   // groupID
    const int tg   = lane & 3;    // threadID_in_group
    const int b    = blockIdx.x * K1_WARPS + wid;

    float* nd  = warpbuf + wid * WBUF_STRIDE;   // [10][68]
    float* uu  = nd + 680;                      // [10][68]  u+b1, later x
    float* vv  = uu + 680;                      // [10][68]
    float* adj = vv + 680;                      // [100]

    // ---- load node: nd[n][f] = hidden[n][b][f] ----
    {
        const float* hb = hidden + (size_t)b * FEAT;
#pragma unroll
        for (int n = 0; n < NCLS; n++) {
            float2 v = *(const float2*)&hb[(size_t)n * BATCH * FEAT + 2 * lane];
            *(float2*)&nd[n * ND_STR + 2 * lane] = v;
        }
    }
    __syncwarp();

    // ---- u/v via mma: [16x64] @ [64x128] (u = cols of W1[0:64], v = W1[64:128]) ----
    {
        float acc[16][4];
#pragma unroll
        for (int nf = 0; nf < 16; nf++)
#pragma unroll
            for (int q = 0; q < 4; q++) acc[nf][q] = 0.f;

#pragma unroll
        for (int kk = 0; kk < 8; kk++) {
            uint32_t A0 = f2tf32(nd[g * ND_STR + kk * 8 + tg]);
            uint32_t A2 = f2tf32(nd[g * ND_STR + kk * 8 + tg + 4]);
            uint32_t A1 = 0u, A3 = 0u;
            if (g < 2) {
                A1 = f2tf32(nd[(g + 8) * ND_STR + kk * 8 + tg]);
                A3 = f2tf32(nd[(g + 8) * ND_STR + kk * 8 + tg + 4]);
            }
#pragma unroll
            for (int nf = 0; nf < 16; nf++) {
                int brow = ((nf & 8) << 3) + kk * 8 + tg;   // +64 rows for v
                int bcol = (nf & 7) * 8 + g;
                uint32_t B0 = sW1[brow * 68 + bcol];
                uint32_t B1 = sW1[(brow + 4) * 68 + bcol];
                MMA_TF32(acc[nf], A0, A1, A2, A3, B0, B1);
            }
        }
#pragma unroll
        for (int nf = 0; nf < 8; nf++) {
            int col = nf * 8 + 2 * tg;
            float bb0 = sb1[col], bb1 = sb1[col + 1];
            *(float2*)&uu[g * ND_STR + col] =
                make_float2(acc[nf][0] + bb0, acc[nf][1] + bb1);
            *(float2*)&vv[g * ND_STR + col] =
                make_float2(acc[nf + 8][0], acc[nf + 8][1]);
            if (g < 2) {
                *(float2*)&uu[(g + 8) * ND_STR + col] =
                    make_float2(acc[nf][2] + bb0, acc[nf][3] + bb1);
                *(float2*)&vv[(g + 8) * ND_STR + col] =
                    make_float2(acc[nf + 8][2], acc[nf + 8][3]);
            }
        }
    }
    __syncwarp();

    // ---- adjacency: adj[i][j] = sigmoid(relu(u_i+v_j).W2 + b2), diag = 1 ----
    {
        const float b2v = smisc[0];
        for (int p = lane; p < 100; p += 32) {
            int i = p / 10, j = p - i * 10;
            float s = b2v;
#pragma unroll 4
            for (int c4 = 0; c4 < 16; c4++) {
                float4 u4 = *(const float4*)&uu[i * ND_STR + 4 * c4];
                float4 v4 = *(const float4*)&vv[j * ND_STR + 4 * c4];
                float4 w4 = *(const float4*)&sW2[4 * c4];
                s = fmaf(fmaxf(u4.x + v4.x, 0.f), w4.x, s);
                s = fmaf(fmaxf(u4.y + v4.y, 0.f), w4.y, s);
                s = fmaf(fmaxf(u4.z + v4.z, 0.f), w4.z, s);
                s = fmaf(fmaxf(u4.w + v4.w, 0.f), w4.w, s);
            }
            adj[p] = (i == j) ? 1.0f : (1.0f / (1.0f + __expf(-s)));
        }
    }
    __syncwarp();

    // ---- x = node + adj @ node  (overwrite uu cols 0..63) ----
    {
        const int f0 = 2 * lane;
        float xa[NCLS], xb[NCLS];
#pragma unroll
        for (int i = 0; i < NCLS; i++) {
            float2 n2 = *(const float2*)&nd[i * ND_STR + f0];
            xa[i] = n2.x; xb[i] = n2.y;
        }
#pragma unroll
        for (int j = 0; j < NCLS; j++) {
            float2 nj = *(const float2*)&nd[j * ND_STR + f0];
#pragma unroll
            for (int i = 0; i < NCLS; i++) {
                float a = adj[i * 10 + j];
                xa[i] = fmaf(a, nj.x, xa[i]);
                xb[i] = fmaf(a, nj.y, xb[i]);
            }
        }
#pragma unroll
        for (int i = 0; i < NCLS; i++)
            *(float2*)&uu[i * ND_STR + f0] = make_float2(xa[i], xb[i]);
    }
    __syncwarp();

    // ---- y = relu(x @ G1 + g1) via mma -> g_Y (tf32, layout [i][b][h]) ----
    {
        float acc[16][4];
#pragma unroll
        for (int nf = 0; nf < 16; nf++)
#pragma unroll
            for (int q = 0; q < 4; q++) acc[nf][q] = 0.f;

#pragma unroll
        for (int kk = 0; kk < 8; kk++) {
            uint32_t A0 = f2tf32(uu[g * ND_STR + kk * 8 + tg]);
            uint32_t A2 = f2tf32(uu[g * ND_STR + kk * 8 + tg + 4]);
            uint32_t A1 = 0u, A3 = 0u;
            if (g < 2) {
                A1 = f2tf32(uu[(g + 8) * ND_STR + kk * 8 + tg]);
                A3 = f2tf32(uu[(g + 8) * ND_STR + kk * 8 + tg + 4]);
            }
#pragma unroll
            for (int nf = 0; nf < 16; nf++) {
                int brow = kk * 8 + tg;
                int bcol = nf * 8 + g;
                uint32_t B0 = sG1[brow * 132 + bcol];
                uint32_t B1 = sG1[(brow + 4) * 132 + bcol];
                MMA_TF32(acc[nf], A0, A1, A2, A3, B0, B1);
            }
        }
#pragma unroll
        for (int nf = 0; nf < 16; nf++) {
            int col = nf * 8 + 2 * tg;
            float gg0 = sg1[col], gg1 = sg1[col + 1];
            uint2 o;
            o.x = f2tf32(fmaxf(acc[nf][0] + gg0, 0.f));
            o.y = f2tf32(fmaxf(acc[nf][1] + gg1, 0.f));
            *(uint2*)&g_Y[((size_t)g * BATCH + b) * 128 + col] = o;
            if (g < 2) {
                uint2 o2;
                o2.x = f2tf32(fmaxf(acc[nf][2] + gg0, 0.f));
                o2.y = f2tf32(fmaxf(acc[nf][3] + gg1, 0.f));
                *(uint2*)&g_Y[((size_t)(g + 8) * BATCH + b) * 128 + col] = o2;
            }
        }
    }
}

// ---------------------------------------------------------------------------
// Kernel 2: out[b] = relu(Y[b] @ E + c0) . D2 + d2, tf32 mma.
// M=8192 (tile 64), N=128, K=1280 (chunk 32). grid=128, 256 threads (8 warps).
// ---------------------------------------------------------------------------
#define AS_STRIDE 36
#define BS_STRIDE 136

__global__ void __launch_bounds__(256, 1) dec_kernel(
    const float* __restrict__ d1, const float* __restrict__ D2,
    const float* __restrict__ d2, float* __restrict__ out)
{
    __shared__ uint32_t As[64 * AS_STRIDE];   // [m=64][k=32]
    __shared__ uint32_t Bs[32 * BS_STRIDE];   // [k=32][n=128]
    __shared__ float rowsum[4][64];

    const int t    = threadIdx.x;
    const int m0   = blockIdx.x * 64;
    const int wid  = t >> 5;
    const int lane = t & 31;
    const int wm   = wid >> 2;
    const int wn   = wid & 3;
    const int g    = lane >> 2;
    const int tg   = lane & 3;

    const int arow = t >> 2;
    const int akc  = (t & 3) * 8;
    const int bkk  = t >> 3;
    const int bn   = (t & 7) * 16;

    float c[2][4][4];
#pragma unroll
    for (int mf = 0; mf < 2; mf++)
#pragma unroll
        for (int nf = 0; nf < 4; nf++)
#pragma unroll
            for (int q = 0; q < 4; q++) c[mf][nf][q] = 0.f;

    for (int k0 = 0; k0 < KTOT; k0 += 32) {
        // A tile: Y layout [i][b][h], i = k0>>7, h0 = k0&127
        {
            const uint32_t* yp = g_Y +
                ((size_t)(k0 >> 7) * BATCH + (m0 + arow)) * 128 + (k0 & 127) + akc;
            uint4 a0 = *(const uint4*)yp;
            uint4 a1 = *(const uint4*)(yp + 4);
            *(uint4*)&As[arow * AS_STRIDE + akc]     = a0;
            *(uint4*)&As[arow * AS_STRIDE + akc + 4] = a1;
        }
        // B tile: E[k0+bkk][bn .. +15]
        {
            const uint32_t* ep = g_E + (size_t)(k0 + bkk) * 128 + bn;
            uint4 e0 = *(const uint4*)ep;
            uint4 e1 = *(const uint4*)(ep + 4);
            uint4 e2 = *(const uint4*)(ep + 8);
            uint4 e3 = *(const uint4*)(ep + 12);
            *(uint4*)&Bs[bkk * BS_STRIDE + bn]      = e0;
            *(uint4*)&Bs[bkk * BS_STRIDE + bn + 4]  = e1;
            *(uint4*)&Bs[bkk * BS_STRIDE + bn + 8]  = e2;
            *(uint4*)&Bs[bkk * BS_STRIDE + bn + 12] = e3;
        }
        __syncthreads();

#pragma unroll
        for (int kk = 0; kk < 32; kk += 8) {
            uint32_t a[2][4], bfr[4][2];
#pragma unroll
            for (int mf = 0; mf < 2; mf++) {
                const uint32_t* ap = &As[(wm * 32 + mf * 16 + g) * AS_STRIDE + kk + tg];
                a[mf][0] = ap[0];
                a[mf][1] = ap[8 * AS_STRIDE];
                a[mf][2] = ap[4];
                a[mf][3] = ap[8 * AS_STRIDE + 4];
            }
#pragma unroll
            for (int nf = 0; nf < 4; nf++) {
                const uint32_t* bp = &Bs[(kk + tg) * BS_STRIDE + wn * 32 + nf * 8 + g];
                bfr[nf][0] = bp[0];
                bfr[nf][1] = bp[4 * BS_STRIDE];
            }
#pragma unroll
            for (int mf = 0; mf < 2; mf++)
#pragma unroll
                for (int nf = 0; nf < 4; nf++)
                    MMA_TF32(c[mf][nf], a[mf][0], a[mf][1], a[mf][2], a[mf][3],
                             bfr[nf][0], bfr[nf][1]);
        }
        __syncthreads();
    }

    float c0v[4][2], d2v[4][2];
#pragma unroll
    for (int nf = 0; nf < 4; nf++) {
#pragma unroll
        for (int j = 0; j < 2; j++) {
            int col = wn * 32 + nf * 8 + tg * 2 + j;
            float base = d1[col];
#pragma unroll
            for (int ii = 0; ii < NCLS; ii++) base += g_c0p[ii * 128 + col];
            c0v[nf][j] = base;
            d2v[nf][j] = D2[col];
        }
    }

#pragma unroll
    for (int mf = 0; mf < 2; mf++) {
        float p0 = 0.f, p1 = 0.f;
#pragma unroll
        for (int nf = 0; nf < 4; nf++) {
            p0 = fmaf(fmaxf(c[mf][nf][0] + c0v[nf][0], 0.f), d2v[nf][0], p0);
            p0 = fmaf(fmaxf(c[mf][nf][1] + c0v[nf][1], 0.f), d2v[nf][1], p0);
            p1 = fmaf(fmaxf(c[mf][nf][2] + c0v[nf][0], 0.f), d2v[nf][0], p1);
            p1 = fmaf(fmaxf(c[mf][nf][3] + c0v[nf][1], 0.f), d2v[nf][1], p1);
        }
        p0 += __shfl_xor_sync(0xffffffffu, p0, 1);
        p0 += __shfl_xor_sync(0xffffffffu, p0, 2);
        p1 += __shfl_xor_sync(0xffffffffu, p1, 1);
        p1 += __shfl_xor_sync(0xffffffffu, p1, 2);
        if (tg == 0) {
            rowsum[wn][wm * 32 + mf * 16 + g]     = p0;
            rowsum[wn][wm * 32 + mf * 16 + g + 8] = p1;
        }
    }
    __syncthreads();

    if (t < 64) {
        float s = rowsum[0][t] + rowsum[1][t] + rowsum[2][t] + rowsum[3][t];
        out[m0 + t] = s + d2[0];
    }
}

// ---------------------------------------------------------------------------
extern "C" void kernel_launch(void* const* d_in, const int* in_sizes, int n_in,
                              void* d_out, int out_size) {
    const float* hidden = (const float*)d_in[1];
    const float* W1 = (const float*)d_in[2];
    const float* b1 = (const float*)d_in[3];
    const float* W2 = (const float*)d_in[4];
    const float* b2 = (const float*)d_in[5];
    const float* G1 = (const float*)d_in[6];
    const float* g1 = (const float*)d_in[7];
    const float* G2 = (const float*)d_in[8];
    const float* g2 = (const float*)d_in[9];
    const float* D1 = (const float*)d_in[10];
    const float* d1 = (const float*)d_in[11];
    const float* D2 = (const float*)d_in[12];
    const float* d2 = (const float*)d_in[13];
    float* out = (float*)d_out;

    const int SMEM1 = (128 * 68 + 64 * 132 + 64 + 64 + 128 + 16 +
                       K1_WARPS * WBUF_STRIDE) * 4;  // 206912 B
    cudaFuncSetAttribute(gnn_kernel, cudaFuncAttributeMaxDynamicSharedMemorySize, SMEM1);

    prep_kernel<<<330, 128>>>(G2, g2, D1);
    gnn_kernel<<<BATCH / K1_WARPS, 512, SMEM1>>>(hidden, W1, b1, W2, b2, G1, g1);
    dec_kernel<<<BATCH / 64, 256>>>(d1, D2, d2, out);
}